// round 3
// baseline (speedup 1.0000x reference)
#include <cuda_runtime.h>

#define NNODES 100000
#define NEDGES 1600000
#define DIN    64
#define DH     128
#define NG     64
#define NEMB   64
#define SCANB  1024
#define NBLK   ((NNODES + SCANB - 1) / SCANB)   // 98

// ---------------- scratch (static device memory; no allocation) ----------------
__device__ float g_agg[(size_t)NNODES * DH];
__device__ float g_h1 [(size_t)NNODES * DH];
__device__ float g_h2 [(size_t)NNODES * DH];
__device__ int   g_deg_i[NNODES];
__device__ int   g_off[NNODES + 1];
__device__ int   g_cursor[NNODES];
__device__ int   g_part[NBLK];
__device__ int   g_csrc[NEDGES];
__device__ float g_pooled[NG * DH];

// ---------------- CSR build ----------------
__global__ void zero_deg_kernel() {
    int i = blockIdx.x * blockDim.x + threadIdx.x;
    if (i < NNODES) g_deg_i[i] = 0;
}

__global__ void hist_kernel(const int* __restrict__ dst) {
    int e = blockIdx.x * blockDim.x + threadIdx.x;
    if (e < NEDGES) atomicAdd(&g_deg_i[dst[e]], 1);
}

__global__ __launch_bounds__(SCANB) void scan_block_kernel() {
    __shared__ int sh[SCANB];
    int i = blockIdx.x * SCANB + threadIdx.x;
    int v = (i < NNODES) ? g_deg_i[i] : 0;
    int x = v;
    sh[threadIdx.x] = x;
    __syncthreads();
#pragma unroll
    for (int d = 1; d < SCANB; d <<= 1) {
        int t = (threadIdx.x >= d) ? sh[threadIdx.x - d] : 0;
        __syncthreads();
        x += t;
        sh[threadIdx.x] = x;
        __syncthreads();
    }
    if (i < NNODES) g_off[i] = x - v;          // exclusive within block
    if (threadIdx.x == SCANB - 1) g_part[blockIdx.x] = x;
}

__global__ void scan_part_kernel() {
    if (threadIdx.x == 0) {
        int run = 0;
        for (int b = 0; b < NBLK; b++) { int t = g_part[b]; g_part[b] = run; run += t; }
    }
}

__global__ void scan_add_kernel() {
    int i = blockIdx.x * blockDim.x + threadIdx.x;
    if (i < NNODES) {
        int o = g_off[i] + g_part[i >> 10];
        g_off[i] = o;
        g_cursor[i] = o;
    }
    if (i == 0) g_off[NNODES] = NEDGES;
}

__global__ void fill_kernel(const int* __restrict__ src,
                            const int* __restrict__ dst) {
    int e = blockIdx.x * blockDim.x + threadIdx.x;
    if (e < NEDGES) {
        int t = dst[e];
        int slot = atomicAdd(&g_cursor[t], 1);
        g_csrc[slot] = src[e];
    }
}

// ---------------- atomic-free aggregation (mean of neighbor features) ----------------
// warp per node; d=128: each lane owns one float4 column chunk
__global__ __launch_bounds__(256) void agg128_kernel(const float* __restrict__ feat) {
    int wid = (blockIdx.x * blockDim.x + threadIdx.x) >> 5;
    int lane = threadIdx.x & 31;
    if (wid >= NNODES) return;
    int s = g_off[wid], e = g_off[wid + 1];
    float4 acc = make_float4(0.f, 0.f, 0.f, 0.f);
    const float4* f4 = (const float4*)feat;
    for (int i = s; i < e; i++) {
        int nb = g_csrc[i];
        float4 v = f4[(size_t)nb * 32 + lane];
        acc.x += v.x; acc.y += v.y; acc.z += v.z; acc.w += v.w;
    }
    float inv = 1.0f / (float)max(e - s, 1);
    acc.x *= inv; acc.y *= inv; acc.z *= inv; acc.w *= inv;
    ((float4*)g_agg)[(size_t)wid * 32 + lane] = acc;
}

// d=64: each lane owns one float2 column chunk
__global__ __launch_bounds__(256) void agg64_kernel(const float* __restrict__ feat) {
    int wid = (blockIdx.x * blockDim.x + threadIdx.x) >> 5;
    int lane = threadIdx.x & 31;
    if (wid >= NNODES) return;
    int s = g_off[wid], e = g_off[wid + 1];
    float2 acc = make_float2(0.f, 0.f);
    const float2* f2 = (const float2*)feat;
    for (int i = s; i < e; i++) {
        int nb = g_csrc[i];
        float2 v = f2[(size_t)nb * 32 + lane];
        acc.x += v.x; acc.y += v.y;
    }
    float inv = 1.0f / (float)max(e - s, 1);
    acc.x *= inv; acc.y *= inv;
    ((float2*)g_agg)[(size_t)wid * 32 + lane] = acc;
}

// ---------------- fused SAGE GEMM ----------------
// out[n, 0:128] = relu( mean[n,:] @ Wl + xin[n,:] @ Wr + b ), Ktot = 2K
#define BM 128
#define BN 128
#define BK 16

__global__ __launch_bounds__(256) void sage_gemm(
    const float* __restrict__ agg, const float* __restrict__ xin,
    const float* __restrict__ Wl, const float* __restrict__ Wr,
    const float* __restrict__ bias, float* __restrict__ out,
    int Nn, int K)
{
    __shared__ float As[BK][BM + 4];
    __shared__ float Ws[BK][BN];

    int tid = threadIdx.x;
    int block_m = blockIdx.x * BM;
    int tm = tid >> 4;
    int tn = tid & 15;

    int la_m   = tid >> 1;
    int la_kkb = (tid & 1) * 8;
    int lw_kk  = tid >> 4;
    int lw_n   = (tid & 15) * 8;

    float acc[8][8];
#pragma unroll
    for (int i = 0; i < 8; i++)
#pragma unroll
        for (int j = 0; j < 8; j++) acc[i][j] = 0.f;

    int Ktot = 2 * K;
    for (int k0 = 0; k0 < Ktot; k0 += BK) {
        {
            int row = block_m + la_m;
            float4 v0 = make_float4(0.f, 0.f, 0.f, 0.f), v1 = v0;
            if (row < Nn) {
                int k = k0 + la_kkb;
                const float* base = (k < K) ? (agg + (size_t)row * K + k)
                                            : (xin + (size_t)row * K + (k - K));
                v0 = ((const float4*)base)[0];
                v1 = ((const float4*)base)[1];
            }
            As[la_kkb + 0][la_m] = v0.x;
            As[la_kkb + 1][la_m] = v0.y;
            As[la_kkb + 2][la_m] = v0.z;
            As[la_kkb + 3][la_m] = v0.w;
            As[la_kkb + 4][la_m] = v1.x;
            As[la_kkb + 5][la_m] = v1.y;
            As[la_kkb + 6][la_m] = v1.z;
            As[la_kkb + 7][la_m] = v1.w;
        }
        {
            int k = k0 + lw_kk;
            const float* wb = (k < K) ? (Wl + (size_t)k * BN + lw_n)
                                      : (Wr + (size_t)(k - K) * BN + lw_n);
            float4 w0 = ((const float4*)wb)[0];
            float4 w1 = ((const float4*)wb)[1];
            ((float4*)&Ws[lw_kk][lw_n])[0] = w0;
            ((float4*)&Ws[lw_kk][lw_n])[1] = w1;
        }
        __syncthreads();

#pragma unroll
        for (int kk = 0; kk < BK; kk++) {
            float a[8], w[8];
            float4 a0 = ((const float4*)&As[kk][tm * 8])[0];
            float4 a1 = ((const float4*)&As[kk][tm * 8])[1];
            a[0] = a0.x; a[1] = a0.y; a[2] = a0.z; a[3] = a0.w;
            a[4] = a1.x; a[5] = a1.y; a[6] = a1.z; a[7] = a1.w;
            float4 w0 = ((const float4*)&Ws[kk][tn * 8])[0];
            float4 w1 = ((const float4*)&Ws[kk][tn * 8])[1];
            w[0] = w0.x; w[1] = w0.y; w[2] = w0.z; w[3] = w0.w;
            w[4] = w1.x; w[5] = w1.y; w[6] = w1.z; w[7] = w1.w;
#pragma unroll
            for (int i = 0; i < 8; i++)
#pragma unroll
                for (int j = 0; j < 8; j++)
                    acc[i][j] += a[i] * w[j];
        }
        __syncthreads();
    }

#pragma unroll
    for (int i = 0; i < 8; i++) {
        int row = block_m + tm * 8 + i;
        if (row < Nn) {
#pragma unroll
            for (int j = 0; j < 8; j += 4) {
                int n = tn * 8 + j;
                float4 r;
                r.x = fmaxf(acc[i][j + 0] + bias[n + 0], 0.f);
                r.y = fmaxf(acc[i][j + 1] + bias[n + 1], 0.f);
                r.z = fmaxf(acc[i][j + 2] + bias[n + 2], 0.f);
                r.w = fmaxf(acc[i][j + 3] + bias[n + 3], 0.f);
                *((float4*)&out[(size_t)row * BN + n]) = r;
            }
        }
    }
}

// ---------------- pooling: block per graph, batch is sorted ----------------
__device__ __forceinline__ int lower_bound_batch(const int* batch, int key) {
    int lo = 0, hi = NNODES;
    while (lo < hi) {
        int mid = (lo + hi) >> 1;
        if (batch[mid] < key) lo = mid + 1; else hi = mid;
    }
    return lo;
}

__global__ __launch_bounds__(DH) void pool_kernel(const int* __restrict__ batch,
                                                  const float* __restrict__ h) {
    __shared__ int s_start, s_end;
    int g = blockIdx.x;
    if (threadIdx.x == 0) s_start = lower_bound_batch(batch, g);
    if (threadIdx.x == 1) s_end   = lower_bound_batch(batch, g + 1);
    __syncthreads();
    int start = s_start, end = s_end;
    float acc = 0.f;
    int col = threadIdx.x;
#pragma unroll 4
    for (int n = start; n < end; n++)
        acc += h[(size_t)n * DH + col];
    g_pooled[g * DH + col] = acc / (float)max(end - start, 1);
}

// ---------------- final MLP ----------------
__global__ __launch_bounds__(NEMB) void mlp_kernel(
    const float* __restrict__ W1, const float* __restrict__ bl1,
    const float* __restrict__ W2, const float* __restrict__ bl2,
    float* __restrict__ out)
{
    __shared__ float p[DH];
    __shared__ float hid[NEMB];
    int g = blockIdx.x;
    int t = threadIdx.x;
    p[t]      = g_pooled[g * DH + t];
    p[t + 64] = g_pooled[g * DH + 64 + t];
    __syncthreads();
    float s = bl1[t];
#pragma unroll 8
    for (int k = 0; k < DH; k++) s += p[k] * W1[k * NEMB + t];
    hid[t] = fmaxf(s, 0.f);
    __syncthreads();
    float o = bl2[t];
#pragma unroll 8
    for (int j = 0; j < NEMB; j++) o += hid[j] * W2[j * NEMB + t];
    out[g * NEMB + t] = o;
}

// ---------------- launch ----------------
extern "C" void kernel_launch(void* const* d_in, const int* in_sizes, int n_in,
                              void* d_out, int out_size) {
    const float* x     = (const float*)d_in[0];
    const int*   ei    = (const int*)d_in[1];      // int32! (JAX x64 disabled)
    const int*   src   = ei;
    const int*   dst   = ei + NEDGES;
    const int*   batch = (const int*)d_in[2];      // int32
    const float *Wl1 = (const float*)d_in[3],  *Wr1 = (const float*)d_in[4],  *b1 = (const float*)d_in[5];
    const float *Wl2 = (const float*)d_in[6],  *Wr2 = (const float*)d_in[7],  *b2 = (const float*)d_in[8];
    const float *Wl3 = (const float*)d_in[9],  *Wr3 = (const float*)d_in[10], *b3 = (const float*)d_in[11];
    const float *W1  = (const float*)d_in[12], *bl1 = (const float*)d_in[13];
    const float *W2  = (const float*)d_in[14], *bl2 = (const float*)d_in[15];

    float* agg;  cudaGetSymbolAddress((void**)&agg, g_agg);
    float* h1;   cudaGetSymbolAddress((void**)&h1,  g_h1);
    float* h2;   cudaGetSymbolAddress((void**)&h2,  g_h2);

    const int T = 256;
    int gemm_blocks = (NNODES + BM - 1) / BM;
    int warp_blocks = (NNODES * 32 + T - 1) / T;

    // ---- CSR build ----
    zero_deg_kernel<<<(NNODES + T - 1) / T, T>>>();
    hist_kernel<<<(NEDGES + T - 1) / T, T>>>(dst);
    scan_block_kernel<<<NBLK, SCANB>>>();
    scan_part_kernel<<<1, 32>>>();
    scan_add_kernel<<<(NNODES + T - 1) / T, T>>>();
    fill_kernel<<<(NEDGES + T - 1) / T, T>>>(src, dst);

    // ---- layer 1 (d=64) ----
    agg64_kernel<<<warp_blocks, T>>>(x);
    sage_gemm<<<gemm_blocks, 256>>>(agg, x, Wl1, Wr1, b1, h1, NNODES, DIN);

    // ---- layer 2 (d=128) ----
    agg128_kernel<<<warp_blocks, T>>>(h1);
    sage_gemm<<<gemm_blocks, 256>>>(agg, h1, Wl2, Wr2, b2, h2, NNODES, DH);

    // ---- layer 3 (d=128) ----
    agg128_kernel<<<warp_blocks, T>>>(h2);
    sage_gemm<<<gemm_blocks, 256>>>(agg, h2, Wl3, Wr3, b3, h1, NNODES, DH);

    // ---- pool + MLP ----
    pool_kernel<<<NG, DH>>>(batch, h1);
    mlp_kernel<<<NG, NEMB>>>(W1, bl1, W2, bl2, (float*)d_out);
}

// round 5
// speedup vs baseline: 1.0098x; 1.0098x over previous
#include <cuda_runtime.h>
#include <cstdint>

#define NNODES 100000
#define NEDGES 1600000
#define DIN    64
#define DH     128
#define NG     64
#define NEMB   64
#define SCANB  1024
#define NBLK   ((NNODES + SCANB - 1) / SCANB)   // 98

typedef unsigned long long ull;

// ---------------- scratch (static device memory; no allocation) ----------------
__device__ float g_agg[(size_t)NNODES * DH];
__device__ float g_h1 [(size_t)NNODES * DH];
__device__ float g_h2 [(size_t)NNODES * DH];
__device__ int   g_deg_i[NNODES];
__device__ int   g_off[NNODES + 1];
__device__ int   g_cursor[NNODES];
__device__ int   g_part[NBLK];
__device__ int   g_csrc[NEDGES];
__device__ float g_pooled[NG * DH];

// ---------------- CSR build ----------------
__global__ void zero_deg_kernel() {
    int i = blockIdx.x * blockDim.x + threadIdx.x;
    if (i < NNODES) g_deg_i[i] = 0;
}
__global__ void hist_kernel(const int* __restrict__ dst) {
    int e = blockIdx.x * blockDim.x + threadIdx.x;
    if (e < NEDGES) atomicAdd(&g_deg_i[dst[e]], 1);
}
__global__ __launch_bounds__(SCANB) void scan_block_kernel() {
    __shared__ int sh[SCANB];
    int i = blockIdx.x * SCANB + threadIdx.x;
    int v = (i < NNODES) ? g_deg_i[i] : 0;
    int x = v;
    sh[threadIdx.x] = x;
    __syncthreads();
#pragma unroll
    for (int d = 1; d < SCANB; d <<= 1) {
        int t = (threadIdx.x >= d) ? sh[threadIdx.x - d] : 0;
        __syncthreads();
        x += t;
        sh[threadIdx.x] = x;
        __syncthreads();
    }
    if (i < NNODES) g_off[i] = x - v;          // exclusive within block
    if (threadIdx.x == SCANB - 1) g_part[blockIdx.x] = x;
}
__global__ __launch_bounds__(128) void scan_part_kernel() {
    __shared__ int sh[128];
    int t = threadIdx.x;
    int v = (t < NBLK) ? g_part[t] : 0;
    int x = v;
    sh[t] = x;
    __syncthreads();
#pragma unroll
    for (int d = 1; d < 128; d <<= 1) {
        int u = (t >= d) ? sh[t - d] : 0;
        __syncthreads();
        x += u;
        sh[t] = x;
        __syncthreads();
    }
    if (t < NBLK) g_part[t] = x - v;   // exclusive
}
__global__ void scan_add_kernel() {
    int i = blockIdx.x * blockDim.x + threadIdx.x;
    if (i < NNODES) {
        int o = g_off[i] + g_part[i >> 10];
        g_off[i] = o;
        g_cursor[i] = o;
    }
    if (i == 0) g_off[NNODES] = NEDGES;
}
__global__ void fill_kernel(const int* __restrict__ src, const int* __restrict__ dst) {
    int e = blockIdx.x * blockDim.x + threadIdx.x;
    if (e < NEDGES) {
        int t = dst[e];
        int slot = atomicAdd(&g_cursor[t], 1);
        g_csrc[slot] = src[e];
    }
}

// ---------------- atomic-free mean aggregation (unrolled x4 for MLP) ----------------
__global__ __launch_bounds__(256) void agg128_kernel(const float* __restrict__ feat) {
    int wid = (blockIdx.x * blockDim.x + threadIdx.x) >> 5;
    int lane = threadIdx.x & 31;
    if (wid >= NNODES) return;
    int s = g_off[wid], e = g_off[wid + 1];
    float4 acc = make_float4(0.f, 0.f, 0.f, 0.f);
    const float4* f4 = (const float4*)feat;
    int i = s;
    for (; i + 4 <= e; i += 4) {
        int n0 = g_csrc[i], n1 = g_csrc[i + 1], n2 = g_csrc[i + 2], n3 = g_csrc[i + 3];
        float4 v0 = f4[(size_t)n0 * 32 + lane];
        float4 v1 = f4[(size_t)n1 * 32 + lane];
        float4 v2 = f4[(size_t)n2 * 32 + lane];
        float4 v3 = f4[(size_t)n3 * 32 + lane];
        acc.x += v0.x + v1.x + v2.x + v3.x;
        acc.y += v0.y + v1.y + v2.y + v3.y;
        acc.z += v0.z + v1.z + v2.z + v3.z;
        acc.w += v0.w + v1.w + v2.w + v3.w;
    }
    for (; i < e; i++) {
        int nb = g_csrc[i];
        float4 v = f4[(size_t)nb * 32 + lane];
        acc.x += v.x; acc.y += v.y; acc.z += v.z; acc.w += v.w;
    }
    float inv = 1.0f / (float)max(e - s, 1);
    acc.x *= inv; acc.y *= inv; acc.z *= inv; acc.w *= inv;
    ((float4*)g_agg)[(size_t)wid * 32 + lane] = acc;
}
__global__ __launch_bounds__(256) void agg64_kernel(const float* __restrict__ feat) {
    int wid = (blockIdx.x * blockDim.x + threadIdx.x) >> 5;
    int lane = threadIdx.x & 31;
    if (wid >= NNODES) return;
    int s = g_off[wid], e = g_off[wid + 1];
    float2 acc = make_float2(0.f, 0.f);
    const float2* f2 = (const float2*)feat;
    int i = s;
    for (; i + 4 <= e; i += 4) {
        int n0 = g_csrc[i], n1 = g_csrc[i + 1], n2 = g_csrc[i + 2], n3 = g_csrc[i + 3];
        float2 v0 = f2[(size_t)n0 * 32 + lane];
        float2 v1 = f2[(size_t)n1 * 32 + lane];
        float2 v2 = f2[(size_t)n2 * 32 + lane];
        float2 v3 = f2[(size_t)n3 * 32 + lane];
        acc.x += v0.x + v1.x + v2.x + v3.x;
        acc.y += v0.y + v1.y + v2.y + v3.y;
    }
    for (; i < e; i++) {
        int nb = g_csrc[i];
        float2 v = f2[(size_t)nb * 32 + lane];
        acc.x += v.x; acc.y += v.y;
    }
    float inv = 1.0f / (float)max(e - s, 1);
    acc.x *= inv; acc.y *= inv;
    ((float2*)g_agg)[(size_t)wid * 32 + lane] = acc;
}

// ---------------- fused SAGE GEMM with packed f32x2 FMA ----------------
// out[n, 0:128] = relu( mean[n,:] @ Wl + xin[n,:] @ Wr + b ), Ktot = 2K
#define BM 128
#define BN 128
#define BK 16

__device__ __forceinline__ void ffma2(ull& acc, ull a2, ull w2) {
    asm("fma.rn.f32x2 %0, %1, %2, %0;" : "+l"(acc) : "l"(a2), "l"(w2));
}
__device__ __forceinline__ ull pack2(float a) {
    ull r;
    asm("mov.b64 %0, {%1, %1};" : "=l"(r) : "r"(__float_as_uint(a)));
    return r;
}

__global__ __launch_bounds__(256) void sage_gemm(
    const float* __restrict__ agg, const float* __restrict__ xin,
    const float* __restrict__ Wl, const float* __restrict__ Wr,
    const float* __restrict__ bias, float* __restrict__ out,
    int Nn, int K)
{
    __shared__ float As[BK][BM + 4];
    __shared__ float Ws[BK][BN];

    int tid = threadIdx.x;
    int block_m = blockIdx.x * BM;
    int tm = tid >> 4;
    int tn = tid & 15;

    int la_m   = tid >> 1;
    int la_kkb = (tid & 1) * 8;
    int lw_kk  = tid >> 4;
    int lw_n   = (tid & 15) * 8;

    ull acc2[8][4];   // [i][jp]: cols (tn*8+2jp, tn*8+2jp+1)
#pragma unroll
    for (int i = 0; i < 8; i++)
#pragma unroll
        for (int j = 0; j < 4; j++) acc2[i][j] = 0ull;

    int Ktot = 2 * K;
    for (int k0 = 0; k0 < Ktot; k0 += BK) {
        {
            int row = block_m + la_m;
            float4 v0 = make_float4(0.f, 0.f, 0.f, 0.f), v1 = v0;
            if (row < Nn) {
                int k = k0 + la_kkb;
                const float* base = (k < K) ? (agg + (size_t)row * K + k)
                                            : (xin + (size_t)row * K + (k - K));
                v0 = ((const float4*)base)[0];
                v1 = ((const float4*)base)[1];
            }
            As[la_kkb + 0][la_m] = v0.x;
            As[la_kkb + 1][la_m] = v0.y;
            As[la_kkb + 2][la_m] = v0.z;
            As[la_kkb + 3][la_m] = v0.w;
            As[la_kkb + 4][la_m] = v1.x;
            As[la_kkb + 5][la_m] = v1.y;
            As[la_kkb + 6][la_m] = v1.z;
            As[la_kkb + 7][la_m] = v1.w;
        }
        {
            int k = k0 + lw_kk;
            const float* wb = (k < K) ? (Wl + (size_t)k * BN + lw_n)
                                      : (Wr + (size_t)(k - K) * BN + lw_n);
            float4 w0 = ((const float4*)wb)[0];
            float4 w1 = ((const float4*)wb)[1];
            ((float4*)&Ws[lw_kk][lw_n])[0] = w0;
            ((float4*)&Ws[lw_kk][lw_n])[1] = w1;
        }
        __syncthreads();

#pragma unroll
        for (int kk = 0; kk < BK; kk++) {
            float4 a0 = ((const float4*)&As[kk][tm * 8])[0];
            float4 a1 = ((const float4*)&As[kk][tm * 8])[1];
            float4 w0 = ((const float4*)&Ws[kk][tn * 8])[0];
            float4 w1 = ((const float4*)&Ws[kk][tn * 8])[1];
            ull w2[4];
            w2[0] = ((ull*)&w0)[0];
            w2[1] = ((ull*)&w0)[1];
            w2[2] = ((ull*)&w1)[0];
            w2[3] = ((ull*)&w1)[1];
            float a[8];
            a[0]=a0.x; a[1]=a0.y; a[2]=a0.z; a[3]=a0.w;
            a[4]=a1.x; a[5]=a1.y; a[6]=a1.z; a[7]=a1.w;
#pragma unroll
            for (int i = 0; i < 8; i++) {
                ull a2 = pack2(a[i]);
#pragma unroll
                for (int j = 0; j < 4; j++)
                    ffma2(acc2[i][j], a2, w2[j]);
            }
        }
        __syncthreads();
    }

#pragma unroll
    for (int i = 0; i < 8; i++) {
        int row = block_m + tm * 8 + i;
        if (row < Nn) {
#pragma unroll
            for (int j = 0; j < 8; j += 4) {
                int n = tn * 8 + j;
                float2 p0 = *(float2*)&acc2[i][j / 2];
                float2 p1 = *(float2*)&acc2[i][j / 2 + 1];
                float4 r;
                r.x = fmaxf(p0.x + bias[n + 0], 0.f);
                r.y = fmaxf(p0.y + bias[n + 1], 0.f);
                r.z = fmaxf(p1.x + bias[n + 2], 0.f);
                r.w = fmaxf(p1.y + bias[n + 3], 0.f);
                *((float4*)&out[(size_t)row * BN + n]) = r;
            }
        }
    }
}

// ---------------- pooling: block per graph, batch is sorted ----------------
__device__ __forceinline__ int lower_bound_batch(const int* batch, int key) {
    int lo = 0, hi = NNODES;
    while (lo < hi) {
        int mid = (lo + hi) >> 1;
        if (batch[mid] < key) lo = mid + 1; else hi = mid;
    }
    return lo;
}
__global__ __launch_bounds__(DH) void pool_kernel(const int* __restrict__ batch,
                                                  const float* __restrict__ h) {
    __shared__ int s_start, s_end;
    int g = blockIdx.x;
    if (threadIdx.x == 0) s_start = lower_bound_batch(batch, g);
    if (threadIdx.x == 1) s_end   = lower_bound_batch(batch, g + 1);
    __syncthreads();
    int start = s_start, end = s_end;
    float acc = 0.f;
    int col = threadIdx.x;
#pragma unroll 4
    for (int n = start; n < end; n++)
        acc += h[(size_t)n * DH + col];
    g_pooled[g * DH + col] = acc / (float)max(end - start, 1);
}

// ---------------- final MLP ----------------
__global__ __launch_bounds__(NEMB) void mlp_kernel(
    const float* __restrict__ W1, const float* __restrict__ bl1,
    const float* __restrict__ W2, const float* __restrict__ bl2,
    float* __restrict__ out)
{
    __shared__ float p[DH];
    __shared__ float hid[NEMB];
    int g = blockIdx.x;
    int t = threadIdx.x;
    p[t]      = g_pooled[g * DH + t];
    p[t + 64] = g_pooled[g * DH + 64 + t];
    __syncthreads();
    float s = bl1[t];
#pragma unroll 8
    for (int k = 0; k < DH; k++) s += p[k] * W1[k * NEMB + t];
    hid[t] = fmaxf(s, 0.f);
    __syncthreads();
    float o = bl2[t];
#pragma unroll 8
    for (int j = 0; j < NEMB; j++) o += hid[j] * W2[j * NEMB + t];
    out[g * NEMB + t] = o;
}

// ---------------- launch ----------------
extern "C" void kernel_launch(void* const* d_in, const int* in_sizes, int n_in,
                              void* d_out, int out_size) {
    const float* x     = (const float*)d_in[0];
    const int*   ei    = (const int*)d_in[1];      // int32 (JAX x64 disabled)
    const int*   src   = ei;
    const int*   dst   = ei + NEDGES;
    const int*   batch = (const int*)d_in[2];
    const float *Wl1 = (const float*)d_in[3],  *Wr1 = (const float*)d_in[4],  *b1 = (const float*)d_in[5];
    const float *Wl2 = (const float*)d_in[6],  *Wr2 = (const float*)d_in[7],  *b2 = (const float*)d_in[8];
    const float *Wl3 = (const float*)d_in[9],  *Wr3 = (const float*)d_in[10], *b3 = (const float*)d_in[11];
    const float *W1  = (const float*)d_in[12], *bl1 = (const float*)d_in[13];
    const float *W2  = (const float*)d_in[14], *bl2 = (const float*)d_in[15];

    float* agg;  cudaGetSymbolAddress((void**)&agg, g_agg);
    float* h1;   cudaGetSymbolAddress((void**)&h1,  g_h1);
    float* h2;   cudaGetSymbolAddress((void**)&h2,  g_h2);

    const int T = 256;
    int gemm_blocks = (NNODES + BM - 1) / BM;
    int warp_blocks = (NNODES * 32 + T - 1) / T;

    // ---- CSR build ----
    zero_deg_kernel<<<(NNODES + T - 1) / T, T>>>();
    hist_kernel<<<(NEDGES + T - 1) / T, T>>>(dst);
    scan_block_kernel<<<NBLK, SCANB>>>();
    scan_part_kernel<<<1, 128>>>();
    scan_add_kernel<<<(NNODES + T - 1) / T, T>>>();
    fill_kernel<<<(NEDGES + T - 1) / T, T>>>(src, dst);

    // ---- layer 1 (d=64) ----
    agg64_kernel<<<warp_blocks, T>>>(x);
    sage_gemm<<<gemm_blocks, 256>>>(agg, x, Wl1, Wr1, b1, h1, NNODES, DIN);

    // ---- layer 2 (d=128) ----
    agg128_kernel<<<warp_blocks, T>>>(h1);
    sage_gemm<<<gemm_blocks, 256>>>(agg, h1, Wl2, Wr2, b2, h2, NNODES, DH);

    // ---- layer 3 ----
    agg128_kernel<<<warp_blocks, T>>>(h2);
    sage_gemm<<<gemm_blocks, 256>>>(agg, h2, Wl3, Wr3, b3, h1, NNODES, DH);

    // ---- pool + MLP ----
    pool_kernel<<<NG, DH>>>(batch, h1);
    mlp_kernel<<<NG, NEMB>>>(W1, bl1, W2, bl2, (float*)d_out);
}